// round 6
// baseline (speedup 1.0000x reference)
#include <cuda_runtime.h>
#include <cuda_bf16.h>
#include <cuda_fp16.h>
#include <cstdint>

#define N_NODES 50000
#define N_EDGES 800000
#define DIM     128
#define NGRAPH  64
#define CSR_CAP (N_EDGES + 8 * N_NODES)   // padded CSR capacity

// ---------------- scratch (static device globals; no allocation) ----------------
__device__ __nv_bfloat16 g_Ahi[N_NODES * DIM];   // GEMM input hi
__device__ __nv_bfloat16 g_Alo[N_NODES * DIM];   // GEMM input lo
__device__ __half        g_hw [N_NODES * DIM];   // GEMM output (SpMM gather input, fp16)
__device__ __nv_bfloat16 g_Whi[3 * DIM * DIM];   // W^T hi  [layer][n][k]
__device__ __nv_bfloat16 g_Wlo[3 * DIM * DIM];   // W^T lo  [layer][n][k]
__device__ int   g_deg[N_NODES];
__device__ float g_dinv[N_NODES];
__device__ int   g_off[N_NODES + 1];
__device__ int   g_cur[N_NODES];
__device__ int   g_csrc[CSR_CAP];
__device__ float g_cnrm[CSR_CAP];
__device__ int   g_is64;
#define PCH 16
__device__ float g_pool[PCH * NGRAPH * DIM];

// ---------------- small helpers ----------------
__device__ __forceinline__ int ldidx(const void* __restrict__ p, long long i) {
    if (g_is64) return (int)((const long long*)p)[i];
    return ((const int*)p)[i];
}
__device__ __forceinline__ uint32_t smem_u32(const void* p) {
    uint32_t a;
    asm("{ .reg .u64 t; cvta.to.shared.u64 t, %1; cvt.u32.u64 %0, t; }" : "=r"(a) : "l"(p));
    return a;
}
__device__ __forceinline__ uint32_t packbf2(float a, float b) {
    __nv_bfloat162 t = __floats2bfloat162_rn(a, b);
    return *reinterpret_cast<uint32_t*>(&t);
}
__device__ __forceinline__ void split2(float a, float b, uint32_t& h, uint32_t& l) {
    h = packbf2(a, b);
    __nv_bfloat162 t = *reinterpret_cast<__nv_bfloat162*>(&h);
    l = packbf2(a - __bfloat162float(t.x), b - __bfloat162float(t.y));
}
__device__ __forceinline__ float2 h2f2(uint32_t u) {
    __half2 h = *reinterpret_cast<__half2*>(&u);
    return __half22float2(h);
}

// ---------------- init + dtype detection (fused) ----------------
__global__ void k_init(const int* __restrict__ probe) {
    int i = blockIdx.x * blockDim.x + threadIdx.x;
    if (i < N_NODES) { g_deg[i] = 0; g_cur[i] = 0; }
    if (blockIdx.x == 0) {
        __shared__ int nz;
        if (threadIdx.x == 0) nz = 0;
        __syncthreads();
        if (threadIdx.x < 256 && probe[threadIdx.x * 2 + 1] != 0) atomicAdd(&nz, 1);
        __syncthreads();
        if (threadIdx.x == 0) g_is64 = (nz == 0) ? 1 : 0;
    }
}

__global__ void k_degree(const void* __restrict__ ei) {
    int e = blockIdx.x * blockDim.x + threadIdx.x;
    if (e < N_EDGES) atomicAdd(&g_deg[ldidx(ei, N_EDGES + e)], 1);
}

// scan with 8-alignment padding; also computes dinv and zero-fills pad slots
__global__ void k_scan() {
    __shared__ int part[1024];
    const int CH = (N_NODES + 1023) / 1024;
    int t = threadIdx.x;
    int b = t * CH;
    int e = b + CH; if (e > N_NODES) e = N_NODES;
    int s = 0;
    for (int i = b; i < e; i++) {
        int d = g_deg[i];
        g_dinv[i] = rsqrtf((float)(d + 1));
        s += (d + 7) & ~7;
    }
    part[t] = s;
    __syncthreads();
    for (int d = 1; d < 1024; d <<= 1) {
        int v = (t >= d) ? part[t - d] : 0;
        __syncthreads();
        part[t] += v;
        __syncthreads();
    }
    int run = (t > 0) ? part[t - 1] : 0;
    for (int i = b; i < e; i++) {
        g_off[i] = run;
        int d = g_deg[i];
        int pd = (d + 7) & ~7;
        for (int j = d; j < pd; j++) { g_csrc[run + j] = 0; g_cnrm[run + j] = 0.f; }
        run += pd;
    }
    if (t == 1023) g_off[N_NODES] = part[1023];
}

// fill CSR; first 48 blocks' threads also transpose/split W (fused prepW)
__global__ void k_fill(const void* __restrict__ ei, const float* __restrict__ W0,
                       const float* __restrict__ W1, const float* __restrict__ W2) {
    int e = blockIdx.x * blockDim.x + threadIdx.x;
    if (e < 3 * DIM * DIM) {
        int L = e >> 14;
        int idx = e & (DIM * DIM - 1);
        const float* W = (L == 0) ? W0 : (L == 1) ? W1 : W2;
        int k = idx >> 7, n = idx & 127;
        float v = W[idx];
        __nv_bfloat16 hi = __float2bfloat16_rn(v);
        float lo = v - __bfloat162float(hi);
        g_Whi[L * DIM * DIM + n * DIM + k] = hi;
        g_Wlo[L * DIM * DIM + n * DIM + k] = __float2bfloat16_rn(lo);
    }
    if (e >= N_EDGES) return;
    int s = ldidx(ei, e);
    int d = ldidx(ei, N_EDGES + e);
    int p = g_off[d] + atomicAdd(&g_cur[d], 1);
    g_csrc[p] = s;
    g_cnrm[p] = g_dinv[s] * g_dinv[d];
}

// ---------------- mma.sync GEMM: g_hw[m][n] = sum_k A[m][k] * W[k][n] ----------------
// bf16 split x split (3 products), fp32 register accumulators, fp16 output.
// Block: 128 threads (4 warps), tile M=64, N=128, K=128. Layer 0 stages from fp32 x.
#define SAS 272                 // smem row stride in BYTES (136 bf16)
#define SM_AH 0
#define SM_AL (SM_AH + 64 * SAS)
#define SM_WH (SM_AL + 64 * SAS)
#define SM_WL (SM_WH + 128 * SAS)
#define SM_TOT (SM_WL + 128 * SAS)

__device__ __forceinline__ void ldsm4(uint32_t addr, uint32_t* r) {
    asm volatile("ldmatrix.sync.aligned.m8n8.x4.shared.b16 {%0,%1,%2,%3}, [%4];"
                 : "=r"(r[0]), "=r"(r[1]), "=r"(r[2]), "=r"(r[3]) : "r"(addr));
}
__device__ __forceinline__ void mma16816(float* d, const uint32_t* a, uint32_t b0, uint32_t b1) {
    asm volatile(
        "mma.sync.aligned.m16n8k16.row.col.f32.bf16.bf16.f32 "
        "{%0,%1,%2,%3}, {%4,%5,%6,%7}, {%8,%9}, {%0,%1,%2,%3};"
        : "+f"(d[0]), "+f"(d[1]), "+f"(d[2]), "+f"(d[3])
        : "r"(a[0]), "r"(a[1]), "r"(a[2]), "r"(a[3]), "r"(b0), "r"(b1));
}

__global__ void __launch_bounds__(128) k_gemm_mma(int layer, const float* __restrict__ xsrc) {
    extern __shared__ char smem[];
    uint32_t sb = smem_u32(smem);
    int tid = threadIdx.x, wid = tid >> 5, lane = tid & 31;
    int m0 = blockIdx.x * 64;
    int valid = N_NODES - m0; if (valid > 64) valid = 64;

    // stage A hi/lo (64 x 128 bf16 each; 16 uint4 per row)
    if (xsrc) {
        #pragma unroll
        for (int i = tid; i < 1024; i += 128) {
            int r = i >> 4, c = i & 15;
            uint4 vh = make_uint4(0, 0, 0, 0), vl = make_uint4(0, 0, 0, 0);
            if (r < valid) {
                const float4* xr = (const float4*)(xsrc + (long long)(m0 + r) * DIM) + c * 2;
                float4 f0 = xr[0], f1 = xr[1];
                split2(f0.x, f0.y, vh.x, vl.x);
                split2(f0.z, f0.w, vh.y, vl.y);
                split2(f1.x, f1.y, vh.z, vl.z);
                split2(f1.z, f1.w, vh.w, vl.w);
            }
            *(uint4*)(smem + SM_AH + r * SAS + c * 16) = vh;
            *(uint4*)(smem + SM_AL + r * SAS + c * 16) = vl;
        }
    } else {
        const uint4* gh = (const uint4*)(g_Ahi + (long long)m0 * DIM);
        const uint4* gl = (const uint4*)(g_Alo + (long long)m0 * DIM);
        #pragma unroll
        for (int i = tid; i < 1024; i += 128) {
            int r = i >> 4, c = i & 15;
            uint4 vh = make_uint4(0, 0, 0, 0), vl = make_uint4(0, 0, 0, 0);
            if (r < valid) { vh = gh[r * 16 + c]; vl = gl[r * 16 + c]; }
            *(uint4*)(smem + SM_AH + r * SAS + c * 16) = vh;
            *(uint4*)(smem + SM_AL + r * SAS + c * 16) = vl;
        }
    }
    {
        const uint4* wh = (const uint4*)(g_Whi + layer * DIM * DIM);
        const uint4* wl = (const uint4*)(g_Wlo + layer * DIM * DIM);
        #pragma unroll
        for (int i = tid; i < 2048; i += 128) {
            int r = i >> 4, c = i & 15;
            *(uint4*)(smem + SM_WH + r * SAS + c * 16) = wh[i];
            *(uint4*)(smem + SM_WL + r * SAS + c * 16) = wl[i];
        }
    }
    __syncthreads();

    float acc[16][4];
    #pragma unroll
    for (int j = 0; j < 16; j++)
        #pragma unroll
        for (int q = 0; q < 4; q++) acc[j][q] = 0.f;

    int wm = wid * 16;
    uint32_t a_off = (uint32_t)((wm + (lane & 15)) * SAS + ((lane >> 4) << 3) * 2);
    uint32_t b_off = (uint32_t)(((lane & 7) + ((lane >> 4) << 3)) * SAS + (((lane >> 3) & 1) << 3) * 2);

    for (int kk = 0; kk < 8; kk++) {
        uint32_t kb = kk * 32;
        uint32_t ah[4], al[4];
        ldsm4(sb + SM_AH + a_off + kb, ah);
        ldsm4(sb + SM_AL + a_off + kb, al);
        #pragma unroll
        for (int nt = 0; nt < 8; nt++) {
            uint32_t bh[4], bl[4];
            uint32_t nrow = nt * 16 * SAS;
            ldsm4(sb + SM_WH + nrow + b_off + kb, bh);
            ldsm4(sb + SM_WL + nrow + b_off + kb, bl);
            mma16816(acc[2 * nt],     ah, bh[0], bh[1]);
            mma16816(acc[2 * nt + 1], ah, bh[2], bh[3]);
            mma16816(acc[2 * nt],     ah, bl[0], bl[1]);
            mma16816(acc[2 * nt + 1], ah, bl[2], bl[3]);
            mma16816(acc[2 * nt],     al, bh[0], bh[1]);
            mma16816(acc[2 * nt + 1], al, bh[2], bh[3]);
        }
    }

    // epilogue: fp16 output
    int r0 = m0 + wm + (lane >> 2);
    int cb = (lane & 3) * 2;
    if (r0 < N_NODES) {
        __half* d = g_hw + (long long)r0 * DIM;
        #pragma unroll
        for (int j = 0; j < 16; j++)
            *(__half2*)(d + j * 8 + cb) = __floats2half2_rn(acc[j][0], acc[j][1]);
    }
    if (r0 + 8 < N_NODES) {
        __half* d = g_hw + (long long)(r0 + 8) * DIM;
        #pragma unroll
        for (int j = 0; j < 16; j++)
            *(__half2*)(d + j * 8 + cb) = __floats2half2_rn(acc[j][2], acc[j][3]);
    }
}

// ---------------- SpMM: fp16 gather (8-wide, aligned), fp32 acc, relu, bf16-split out ----
__device__ __forceinline__ void acc_edge(float4& acc, float n, uint2 v) {
    float2 a = h2f2(v.x), b = h2f2(v.y);
    acc.x += n * a.x; acc.y += n * a.y; acc.z += n * b.x; acc.w += n * b.y;
}

__global__ void __launch_bounds__(256) k_spmm(const float* __restrict__ bias) {
    int warp = (blockIdx.x * blockDim.x + threadIdx.x) >> 5;
    int lane = threadIdx.x & 31;
    if (warp >= N_NODES) return;
    int i = warp;

    float di = g_dinv[i];
    float sl = di * di;
    float4 acc;
    {
        uint2 v = ((const uint2*)(g_hw + (long long)i * DIM))[lane];
        float2 a = h2f2(v.x), b = h2f2(v.y);
        acc = make_float4(sl * a.x, sl * a.y, sl * b.x, sl * b.y);
    }

    int p = g_off[i], pe = g_off[i + 1];
    for (; p < pe; p += 8) {     // segment length is always a multiple of 8
        int4   c0 = *(const int4*)(g_csrc + p);
        int4   c1 = *(const int4*)(g_csrc + p + 4);
        float4 n0 = *(const float4*)(g_cnrm + p);
        float4 n1 = *(const float4*)(g_cnrm + p + 4);
        uint2 v0 = ((const uint2*)(g_hw + (long long)c0.x * DIM))[lane];
        uint2 v1 = ((const uint2*)(g_hw + (long long)c0.y * DIM))[lane];
        uint2 v2 = ((const uint2*)(g_hw + (long long)c0.z * DIM))[lane];
        uint2 v3 = ((const uint2*)(g_hw + (long long)c0.w * DIM))[lane];
        uint2 v4 = ((const uint2*)(g_hw + (long long)c1.x * DIM))[lane];
        uint2 v5 = ((const uint2*)(g_hw + (long long)c1.y * DIM))[lane];
        uint2 v6 = ((const uint2*)(g_hw + (long long)c1.z * DIM))[lane];
        uint2 v7 = ((const uint2*)(g_hw + (long long)c1.w * DIM))[lane];
        acc_edge(acc, n0.x, v0);
        acc_edge(acc, n0.y, v1);
        acc_edge(acc, n0.z, v2);
        acc_edge(acc, n0.w, v3);
        acc_edge(acc, n1.x, v4);
        acc_edge(acc, n1.y, v5);
        acc_edge(acc, n1.z, v6);
        acc_edge(acc, n1.w, v7);
    }

    float4 bv = ((const float4*)bias)[lane];
    acc.x = fmaxf(acc.x + bv.x, 0.f);
    acc.y = fmaxf(acc.y + bv.y, 0.f);
    acc.z = fmaxf(acc.z + bv.z, 0.f);
    acc.w = fmaxf(acc.w + bv.w, 0.f);

    // bf16 split store for next layer's GEMM (and pool)
    uint2 ph, pl;
    split2(acc.x, acc.y, ph.x, pl.x);
    split2(acc.z, acc.w, ph.y, pl.y);
    ((uint2*)g_Ahi)[(long long)i * 32 + lane] = ph;
    ((uint2*)g_Alo)[(long long)i * 32 + lane] = pl;
}

// ---------------- global mean pool (batch is sorted; no atomics) ----------------
__device__ __forceinline__ int lbound(const void* __restrict__ b, int key) {
    int lo = 0, hi = N_NODES;
    while (lo < hi) {
        int mid = (lo + hi) >> 1;
        if (ldidx(b, mid) < key) lo = mid + 1; else hi = mid;
    }
    return lo;
}
__global__ void k_pool(const void* __restrict__ batch) {
    int g = blockIdx.x / PCH;
    int c = blockIdx.x % PCH;
    int t = threadIdx.x;
    int start = lbound(batch, g);
    int end   = lbound(batch, g + 1);
    int len = end - start;
    int rs = start + (int)((long long)len * c / PCH);
    int re = start + (int)((long long)len * (c + 1) / PCH);
    float s = 0.f;
    for (int r = rs; r < re; r++) {
        long long idx = (long long)r * DIM + t;
        s += __bfloat162float(g_Ahi[idx]) + __bfloat162float(g_Alo[idx]);
    }
    g_pool[(c * NGRAPH + g) * DIM + t] = s;
}
__global__ void k_pool_div(const void* __restrict__ batch, float* __restrict__ out) {
    int g = blockIdx.x;
    int t = threadIdx.x;
    float s = 0.f;
    #pragma unroll
    for (int c = 0; c < PCH; c++) s += g_pool[(c * NGRAPH + g) * DIM + t];
    int start = lbound(batch, g);
    int end   = lbound(batch, g + 1);
    float cnt = (float)(end - start);
    if (cnt < 1.f) cnt = 1.f;
    out[g * DIM + t] = s / cnt;
}

// ---------------- launch ----------------
extern "C" void kernel_launch(void* const* d_in, const int* in_sizes, int n_in,
                              void* d_out, int out_size) {
    (void)out_size;
    const float* x = 0; const void* ei = 0; const void* batch = 0;
    const float* W[3] = {0, 0, 0}; const float* b[3] = {0, 0, 0};
    int nw = 0, nb = 0;
    for (int i = 0; i < n_in; i++) {
        int sz = in_sizes[i];
        if      (sz == N_NODES * DIM) x     = (const float*)d_in[i];
        else if (sz == 2 * N_EDGES)   ei    = d_in[i];
        else if (sz == N_NODES)       batch = d_in[i];
        else if (sz == DIM * DIM)     { if (nw < 3) W[nw++] = (const float*)d_in[i]; }
        else if (sz == DIM)           { if (nb < 3) b[nb++] = (const float*)d_in[i]; }
    }
    float* out = (float*)d_out;

    cudaFuncSetAttribute(k_gemm_mma, cudaFuncAttributeMaxDynamicSharedMemorySize, SM_TOT);

    const int NT = 256;
    int nblk = (N_NODES + NT - 1) / NT;
    int eblk = (N_EDGES + NT - 1) / NT;
    int spmm_blocks = (N_NODES * 32 + NT - 1) / NT;
    int gemm_blocks = (N_NODES + 63) / 64;  // 782

    // preprocess (5 launches)
    k_init<<<nblk, NT>>>((const int*)ei);
    k_degree<<<eblk, NT>>>(ei);
    k_scan<<<1, 1024>>>();
    k_fill<<<eblk, NT>>>(ei, W[0], W[1], W[2]);

    // layers (6 launches); layer 0 stages directly from fp32 x
    k_gemm_mma<<<gemm_blocks, 128, SM_TOT>>>(0, x);
    k_spmm<<<spmm_blocks, NT>>>(b[0]);
    k_gemm_mma<<<gemm_blocks, 128, SM_TOT>>>(1, nullptr);
    k_spmm<<<spmm_blocks, NT>>>(b[1]);
    k_gemm_mma<<<gemm_blocks, 128, SM_TOT>>>(2, nullptr);
    k_spmm<<<spmm_blocks, NT>>>(b[2]);

    // pool (2 launches, no atomics)
    k_pool<<<NGRAPH * PCH, DIM>>>(batch);
    k_pool_div<<<NGRAPH, DIM>>>(batch, out);
}

// round 7
// speedup vs baseline: 1.6366x; 1.6366x over previous
#include <cuda_runtime.h>
#include <cuda_bf16.h>
#include <cuda_fp16.h>
#include <cstdint>

#define N_NODES 50000
#define N_EDGES 800000
#define DIM     128
#define NGRAPH  64
#define CSR_CAP (N_EDGES + 8 * N_NODES)   // padded CSR capacity

// ---------------- scratch (static device globals; no allocation) ----------------
__device__ __nv_bfloat16 g_Ahi[N_NODES * DIM];   // GEMM input hi
__device__ __nv_bfloat16 g_Alo[N_NODES * DIM];   // GEMM input lo
__device__ __half        g_hw [N_NODES * DIM];   // GEMM output (SpMM gather input, fp16)
__device__ __nv_bfloat16 g_Whi[3 * DIM * DIM];   // W^T hi  [layer][n][k]
__device__ __nv_bfloat16 g_Wlo[3 * DIM * DIM];   // W^T lo  [layer][n][k]
__device__ int   g_deg[N_NODES];
__device__ float g_dinv[N_NODES];
__device__ int   g_off[N_NODES + 1];
__device__ int   g_cur[N_NODES];
__device__ int   g_csrc[CSR_CAP];
__device__ float g_cnrm[CSR_CAP];
__device__ int   g_is64;
#define PCH 16
__device__ float g_pool[PCH * NGRAPH * DIM];

// ---------------- small helpers ----------------
__device__ __forceinline__ int ldidx(const void* __restrict__ p, long long i) {
    if (g_is64) return (int)((const long long*)p)[i];
    return ((const int*)p)[i];
}
__device__ __forceinline__ uint32_t smem_u32(const void* p) {
    uint32_t a;
    asm("{ .reg .u64 t; cvta.to.shared.u64 t, %1; cvt.u32.u64 %0, t; }" : "=r"(a) : "l"(p));
    return a;
}
__device__ __forceinline__ uint32_t packbf2(float a, float b) {
    __nv_bfloat162 t = __floats2bfloat162_rn(a, b);
    return *reinterpret_cast<uint32_t*>(&t);
}
__device__ __forceinline__ void split2(float a, float b, uint32_t& h, uint32_t& l) {
    h = packbf2(a, b);
    __nv_bfloat162 t = *reinterpret_cast<__nv_bfloat162*>(&h);
    l = packbf2(a - __bfloat162float(t.x), b - __bfloat162float(t.y));
}
__device__ __forceinline__ float2 h2f2(uint32_t u) {
    __half2 h = *reinterpret_cast<__half2*>(&u);
    return __half22float2(h);
}

// ---------------- init + dtype detection (fused) ----------------
__global__ void k_init(const int* __restrict__ probe) {
    int i = blockIdx.x * blockDim.x + threadIdx.x;
    if (i < N_NODES) { g_deg[i] = 0; g_cur[i] = 0; }
    if (blockIdx.x == 0) {
        __shared__ int nz;
        if (threadIdx.x == 0) nz = 0;
        __syncthreads();
        if (threadIdx.x < 256 && probe[threadIdx.x * 2 + 1] != 0) atomicAdd(&nz, 1);
        __syncthreads();
        if (threadIdx.x == 0) g_is64 = (nz == 0) ? 1 : 0;
    }
}

__global__ void k_degree(const void* __restrict__ ei) {
    int e = blockIdx.x * blockDim.x + threadIdx.x;
    if (e < N_EDGES) atomicAdd(&g_deg[ldidx(ei, N_EDGES + e)], 1);
}

// scan with 8-alignment padding: offsets + dinv ONLY (no CSR stores — those are parallel in k_pad)
__global__ void k_scan() {
    __shared__ int part[1024];
    const int CH = (N_NODES + 1023) / 1024;
    int t = threadIdx.x;
    int b = t * CH;
    int e = b + CH; if (e > N_NODES) e = N_NODES;
    int s = 0;
    for (int i = b; i < e; i++) {
        int d = g_deg[i];
        g_dinv[i] = rsqrtf((float)(d + 1));
        s += (d + 7) & ~7;
    }
    part[t] = s;
    __syncthreads();
    for (int d = 1; d < 1024; d <<= 1) {
        int v = (t >= d) ? part[t - d] : 0;
        __syncthreads();
        part[t] += v;
        __syncthreads();
    }
    int run = (t > 0) ? part[t - 1] : 0;
    for (int i = b; i < e; i++) {
        g_off[i] = run;
        run += (g_deg[i] + 7) & ~7;
    }
    if (t == 1023) g_off[N_NODES] = part[1023];
}

// parallel pad fill: zero the padding slots of each node's CSR segment
__global__ void k_pad() {
    int i = blockIdx.x * blockDim.x + threadIdx.x;
    if (i >= N_NODES) return;
    int off = g_off[i];
    int d = g_deg[i];
    int pd = (d + 7) & ~7;
    for (int j = d; j < pd; j++) { g_csrc[off + j] = 0; g_cnrm[off + j] = 0.f; }
}

// fill CSR; low-index threads also transpose/split W (fused prepW)
__global__ void k_fill(const void* __restrict__ ei, const float* __restrict__ W0,
                       const float* __restrict__ W1, const float* __restrict__ W2) {
    int e = blockIdx.x * blockDim.x + threadIdx.x;
    if (e < 3 * DIM * DIM) {
        int L = e >> 14;
        int idx = e & (DIM * DIM - 1);
        const float* W = (L == 0) ? W0 : (L == 1) ? W1 : W2;
        int k = idx >> 7, n = idx & 127;
        float v = W[idx];
        __nv_bfloat16 hi = __float2bfloat16_rn(v);
        float lo = v - __bfloat162float(hi);
        g_Whi[L * DIM * DIM + n * DIM + k] = hi;
        g_Wlo[L * DIM * DIM + n * DIM + k] = __float2bfloat16_rn(lo);
    }
    if (e >= N_EDGES) return;
    int s = ldidx(ei, e);
    int d = ldidx(ei, N_EDGES + e);
    int p = g_off[d] + atomicAdd(&g_cur[d], 1);
    g_csrc[p] = s;
    g_cnrm[p] = g_dinv[s] * g_dinv[d];
}

// ---------------- mma.sync GEMM: g_hw[m][n] = sum_k A[m][k] * W[k][n] ----------------
// bf16 split x split (3 products), fp32 register accumulators, fp16 output.
// Block: 128 threads (4 warps), tile M=64, N=128, K=128. Layer 0 stages from fp32 x.
#define SAS 272                 // smem row stride in BYTES (136 bf16)
#define SM_AH 0
#define SM_AL (SM_AH + 64 * SAS)
#define SM_WH (SM_AL + 64 * SAS)
#define SM_WL (SM_WH + 128 * SAS)
#define SM_TOT (SM_WL + 128 * SAS)

__device__ __forceinline__ void ldsm4(uint32_t addr, uint32_t* r) {
    asm volatile("ldmatrix.sync.aligned.m8n8.x4.shared.b16 {%0,%1,%2,%3}, [%4];"
                 : "=r"(r[0]), "=r"(r[1]), "=r"(r[2]), "=r"(r[3]) : "r"(addr));
}
__device__ __forceinline__ void mma16816(float* d, const uint32_t* a, uint32_t b0, uint32_t b1) {
    asm volatile(
        "mma.sync.aligned.m16n8k16.row.col.f32.bf16.bf16.f32 "
        "{%0,%1,%2,%3}, {%4,%5,%6,%7}, {%8,%9}, {%0,%1,%2,%3};"
        : "+f"(d[0]), "+f"(d[1]), "+f"(d[2]), "+f"(d[3])
        : "r"(a[0]), "r"(a[1]), "r"(a[2]), "r"(a[3]), "r"(b0), "r"(b1));
}

__global__ void __launch_bounds__(128) k_gemm_mma(int layer, const float* __restrict__ xsrc) {
    extern __shared__ char smem[];
    uint32_t sb = smem_u32(smem);
    int tid = threadIdx.x, wid = tid >> 5, lane = tid & 31;
    int m0 = blockIdx.x * 64;
    int valid = N_NODES - m0; if (valid > 64) valid = 64;

    // stage A hi/lo (64 x 128 bf16 each; 16 uint4 per row)
    if (xsrc) {
        #pragma unroll
        for (int i = tid; i < 1024; i += 128) {
            int r = i >> 4, c = i & 15;
            uint4 vh = make_uint4(0, 0, 0, 0), vl = make_uint4(0, 0, 0, 0);
            if (r < valid) {
                const float4* xr = (const float4*)(xsrc + (long long)(m0 + r) * DIM) + c * 2;
                float4 f0 = xr[0], f1 = xr[1];
                split2(f0.x, f0.y, vh.x, vl.x);
                split2(f0.z, f0.w, vh.y, vl.y);
                split2(f1.x, f1.y, vh.z, vl.z);
                split2(f1.z, f1.w, vh.w, vl.w);
            }
            *(uint4*)(smem + SM_AH + r * SAS + c * 16) = vh;
            *(uint4*)(smem + SM_AL + r * SAS + c * 16) = vl;
        }
    } else {
        const uint4* gh = (const uint4*)(g_Ahi + (long long)m0 * DIM);
        const uint4* gl = (const uint4*)(g_Alo + (long long)m0 * DIM);
        #pragma unroll
        for (int i = tid; i < 1024; i += 128) {
            int r = i >> 4, c = i & 15;
            uint4 vh = make_uint4(0, 0, 0, 0), vl = make_uint4(0, 0, 0, 0);
            if (r < valid) { vh = gh[r * 16 + c]; vl = gl[r * 16 + c]; }
            *(uint4*)(smem + SM_AH + r * SAS + c * 16) = vh;
            *(uint4*)(smem + SM_AL + r * SAS + c * 16) = vl;
        }
    }
    {
        const uint4* wh = (const uint4*)(g_Whi + layer * DIM * DIM);
        const uint4* wl = (const uint4*)(g_Wlo + layer * DIM * DIM);
        #pragma unroll
        for (int i = tid; i < 2048; i += 128) {
            int r = i >> 4, c = i & 15;
            *(uint4*)(smem + SM_WH + r * SAS + c * 16) = wh[i];
            *(uint4*)(smem + SM_WL + r * SAS + c * 16) = wl[i];
        }
    }
    __syncthreads();

    float acc[16][4];
    #pragma unroll
    for (int j = 0; j < 16; j++)
        #pragma unroll
        for (int q = 0; q < 4; q++) acc[j][q] = 0.f;

    int wm = wid * 16;
    uint32_t a_off = (uint32_t)((wm + (lane & 15)) * SAS + ((lane >> 4) << 3) * 2);
    uint32_t b_off = (uint32_t)(((lane & 7) + ((lane >> 4) << 3)) * SAS + (((lane >> 3) & 1) << 3) * 2);

    for (int kk = 0; kk < 8; kk++) {
        uint32_t kb = kk * 32;
        uint32_t ah[4], al[4];
        ldsm4(sb + SM_AH + a_off + kb, ah);
        ldsm4(sb + SM_AL + a_off + kb, al);
        #pragma unroll
        for (int nt = 0; nt < 8; nt++) {
            uint32_t bh[4], bl[4];
            uint32_t nrow = nt * 16 * SAS;
            ldsm4(sb + SM_WH + nrow + b_off + kb, bh);
            ldsm4(sb + SM_WL + nrow + b_off + kb, bl);
            mma16816(acc[2 * nt],     ah, bh[0], bh[1]);
            mma16816(acc[2 * nt + 1], ah, bh[2], bh[3]);
            mma16816(acc[2 * nt],     ah, bl[0], bl[1]);
            mma16816(acc[2 * nt + 1], ah, bl[2], bl[3]);
            mma16816(acc[2 * nt],     al, bh[0], bh[1]);
            mma16816(acc[2 * nt + 1], al, bh[2], bh[3]);
        }
    }

    // epilogue: fp16 output
    int r0 = m0 + wm + (lane >> 2);
    int cb = (lane & 3) * 2;
    if (r0 < N_NODES) {
        __half* d = g_hw + (long long)r0 * DIM;
        #pragma unroll
        for (int j = 0; j < 16; j++)
            *(__half2*)(d + j * 8 + cb) = __floats2half2_rn(acc[j][0], acc[j][1]);
    }
    if (r0 + 8 < N_NODES) {
        __half* d = g_hw + (long long)(r0 + 8) * DIM;
        #pragma unroll
        for (int j = 0; j < 16; j++)
            *(__half2*)(d + j * 8 + cb) = __floats2half2_rn(acc[j][2], acc[j][3]);
    }
}

// ---------------- SpMM: fp16 gather (8-wide, aligned), fp32 acc, relu, bf16-split out ----
__device__ __forceinline__ void acc_edge(float4& acc, float n, uint2 v) {
    float2 a = h2f2(v.x), b = h2f2(v.y);
    acc.x += n * a.x; acc.y += n * a.y; acc.z += n * b.x; acc.w += n * b.y;
}

__global__ void __launch_bounds__(256) k_spmm(const float* __restrict__ bias) {
    int warp = (blockIdx.x * blockDim.x + threadIdx.x) >> 5;
    int lane = threadIdx.x & 31;
    if (warp >= N_NODES) return;
    int i = warp;

    float di = g_dinv[i];
    float sl = di * di;
    float4 acc;
    {
        uint2 v = ((const uint2*)(g_hw + (long long)i * DIM))[lane];
        float2 a = h2f2(v.x), b = h2f2(v.y);
        acc = make_float4(sl * a.x, sl * a.y, sl * b.x, sl * b.y);
    }

    int p = g_off[i], pe = g_off[i + 1];
    for (; p < pe; p += 8) {     // segment length is always a multiple of 8
        int4   c0 = *(const int4*)(g_csrc + p);
        int4   c1 = *(const int4*)(g_csrc + p + 4);
        float4 n0 = *(const float4*)(g_cnrm + p);
        float4 n1 = *(const float4*)(g_cnrm + p + 4);
        uint2 v0 = ((const uint2*)(g_hw + (long long)c0.x * DIM))[lane];
        uint2 v1 = ((const uint2*)(g_hw + (long long)c0.y * DIM))[lane];
        uint2 v2 = ((const uint2*)(g_hw + (long long)c0.z * DIM))[lane];
        uint2 v3 = ((const uint2*)(g_hw + (long long)c0.w * DIM))[lane];
        uint2 v4 = ((const uint2*)(g_hw + (long long)c1.x * DIM))[lane];
        uint2 v5 = ((const uint2*)(g_hw + (long long)c1.y * DIM))[lane];
        uint2 v6 = ((const uint2*)(g_hw + (long long)c1.z * DIM))[lane];
        uint2 v7 = ((const uint2*)(g_hw + (long long)c1.w * DIM))[lane];
        acc_edge(acc, n0.x, v0);
        acc_edge(acc, n0.y, v1);
        acc_edge(acc, n0.z, v2);
        acc_edge(acc, n0.w, v3);
        acc_edge(acc, n1.x, v4);
        acc_edge(acc, n1.y, v5);
        acc_edge(acc, n1.z, v6);
        acc_edge(acc, n1.w, v7);
    }

    float4 bv = ((const float4*)bias)[lane];
    acc.x = fmaxf(acc.x + bv.x, 0.f);
    acc.y = fmaxf(acc.y + bv.y, 0.f);
    acc.z = fmaxf(acc.z + bv.z, 0.f);
    acc.w = fmaxf(acc.w + bv.w, 0.f);

    // bf16 split store for next layer's GEMM (and pool)
    uint2 ph, pl;
    split2(acc.x, acc.y, ph.x, pl.x);
    split2(acc.z, acc.w, ph.y, pl.y);
    ((uint2*)g_Ahi)[(long long)i * 32 + lane] = ph;
    ((uint2*)g_Alo)[(long long)i * 32 + lane] = pl;
}

// ---------------- global mean pool (batch is sorted; no atomics) ----------------
__device__ __forceinline__ int lbound(const void* __restrict__ b, int key) {
    int lo = 0, hi = N_NODES;
    while (lo < hi) {
        int mid = (lo + hi) >> 1;
        if (ldidx(b, mid) < key) lo = mid + 1; else hi = mid;
    }
    return lo;
}
__global__ void k_pool(const void* __restrict__ batch) {
    int g = blockIdx.x / PCH;
    int c = blockIdx.x % PCH;
    int t = threadIdx.x;
    int start = lbound(batch, g);
    int end   = lbound(batch, g + 1);
    int len = end - start;
    int rs = start + (int)((long long)len * c / PCH);
    int re = start + (int)((long long)len * (c + 1) / PCH);
    float s = 0.f;
    for (int r = rs; r < re; r++) {
        long long idx = (long long)r * DIM + t;
        s += __bfloat162float(g_Ahi[idx]) + __bfloat162float(g_Alo[idx]);
    }
    g_pool[(c * NGRAPH + g) * DIM + t] = s;
}
__global__ void k_pool_div(const void* __restrict__ batch, float* __restrict__ out) {
    int g = blockIdx.x;
    int t = threadIdx.x;
    float s = 0.f;
    #pragma unroll
    for (int c = 0; c < PCH; c++) s += g_pool[(c * NGRAPH + g) * DIM + t];
    int start = lbound(batch, g);
    int end   = lbound(batch, g + 1);
    float cnt = (float)(end - start);
    if (cnt < 1.f) cnt = 1.f;
    out[g * DIM + t] = s / cnt;
}

// ---------------- launch ----------------
extern "C" void kernel_launch(void* const* d_in, const int* in_sizes, int n_in,
                              void* d_out, int out_size) {
    (void)out_size;
    const float* x = 0; const void* ei = 0; const void* batch = 0;
    const float* W[3] = {0, 0, 0}; const float* b[3] = {0, 0, 0};
    int nw = 0, nb = 0;
    for (int i = 0; i < n_in; i++) {
        int sz = in_sizes[i];
        if      (sz == N_NODES * DIM) x     = (const float*)d_in[i];
        else if (sz == 2 * N_EDGES)   ei    = d_in[i];
        else if (sz == N_NODES)       batch = d_in[i];
        else if (sz == DIM * DIM)     { if (nw < 3) W[nw++] = (const float*)d_in[i]; }
        else if (sz == DIM)           { if (nb < 3) b[nb++] = (const float*)d_in[i]; }
    }
    float* out = (float*)d_out;

    cudaFuncSetAttribute(k_gemm_mma, cudaFuncAttributeMaxDynamicSharedMemorySize, SM_TOT);

    const int NT = 256;
    int nblk = (N_NODES + NT - 1) / NT;
    int eblk = (N_EDGES + NT - 1) / NT;
    int spmm_blocks = (N_NODES * 32 + NT - 1) / NT;
    int gemm_blocks = (N_NODES + 63) / 64;  // 782

    // preprocess (5 launches)
    k_init<<<nblk, NT>>>((const int*)ei);
    k_degree<<<eblk, NT>>>(ei);
    k_scan<<<1, 1024>>>();
    k_pad<<<nblk, NT>>>();
    k_fill<<<eblk, NT>>>(ei, W[0], W[1], W[2]);

    // layers (6 launches); layer 0 stages directly from fp32 x
    k_gemm_mma<<<gemm_blocks, 128, SM_TOT>>>(0, x);
    k_spmm<<<spmm_blocks, NT>>>(b[0]);
    k_gemm_mma<<<gemm_blocks, 128, SM_TOT>>>(1, nullptr);
    k_spmm<<<spmm_blocks, NT>>>(b[1]);
    k_gemm_mma<<<gemm_blocks, 128, SM_TOT>>>(2, nullptr);
    k_spmm<<<spmm_blocks, NT>>>(b[2]);

    // pool (2 launches, no atomics)
    k_pool<<<NGRAPH * PCH, DIM>>>(batch);
    k_pool_div<<<NGRAPH, DIM>>>(batch, out);
}

// round 8
// speedup vs baseline: 1.7355x; 1.0604x over previous
#include <cuda_runtime.h>
#include <cuda_bf16.h>
#include <cuda_fp16.h>
#include <cstdint>

#define N_NODES 50000
#define N_EDGES 800000
#define DIM     128
#define NGRAPH  64

// ---------------- scratch (static device globals; no allocation) ----------------
__device__ __nv_bfloat16 g_Ahi[N_NODES * DIM];   // GEMM input hi
__device__ __nv_bfloat16 g_Alo[N_NODES * DIM];   // GEMM input lo
__device__ __half        g_hw [N_NODES * DIM];   // GEMM output (SpMM gather input, fp16)
__device__ __nv_bfloat16 g_Whi[3 * DIM * DIM];   // W^T hi  [layer][n][k]
__device__ __nv_bfloat16 g_Wlo[3 * DIM * DIM];   // W^T lo  [layer][n][k]
__device__ int   g_deg[N_NODES];
__device__ float g_dinv[N_NODES];
__device__ int   g_off[N_NODES + 1];
__device__ int   g_cur[N_NODES];
__device__ int   g_csrc[N_EDGES];
__device__ float g_cnrm[N_EDGES];
__device__ int   g_is64;
#define PCH 16
__device__ float g_pool[PCH * NGRAPH * DIM];

// ---------------- small helpers ----------------
__device__ __forceinline__ int ldidx(const void* __restrict__ p, long long i) {
    if (g_is64) return (int)((const long long*)p)[i];
    return ((const int*)p)[i];
}
__device__ __forceinline__ uint32_t smem_u32(const void* p) {
    uint32_t a;
    asm("{ .reg .u64 t; cvta.to.shared.u64 t, %1; cvt.u32.u64 %0, t; }" : "=r"(a) : "l"(p));
    return a;
}
__device__ __forceinline__ uint32_t packbf2(float a, float b) {
    __nv_bfloat162 t = __floats2bfloat162_rn(a, b);
    return *reinterpret_cast<uint32_t*>(&t);
}
__device__ __forceinline__ void split2(float a, float b, uint32_t& h, uint32_t& l) {
    h = packbf2(a, b);
    __nv_bfloat162 t = *reinterpret_cast<__nv_bfloat162*>(&h);
    l = packbf2(a - __bfloat162float(t.x), b - __bfloat162float(t.y));
}
__device__ __forceinline__ float2 h2f2(uint32_t u) {
    __half2 h = *reinterpret_cast<__half2*>(&u);
    return __half22float2(h);
}

// ---------------- init + dtype detection (fused) ----------------
__global__ void k_init(const int* __restrict__ probe) {
    int i = blockIdx.x * blockDim.x + threadIdx.x;
    if (i < N_NODES) { g_deg[i] = 0; g_cur[i] = 0; }
    if (blockIdx.x == 0) {
        __shared__ int nz;
        if (threadIdx.x == 0) nz = 0;
        __syncthreads();
        if (threadIdx.x < 256 && probe[threadIdx.x * 2 + 1] != 0) atomicAdd(&nz, 1);
        __syncthreads();
        if (threadIdx.x == 0) g_is64 = (nz == 0) ? 1 : 0;
    }
}

__global__ void k_degree(const void* __restrict__ ei) {
    int e = blockIdx.x * blockDim.x + threadIdx.x;
    if (e < N_EDGES) atomicAdd(&g_deg[ldidx(ei, N_EDGES + e)], 1);
}

// plain scan (no padding); dinv fused
__global__ void k_scan() {
    __shared__ int part[1024];
    const int CH = (N_NODES + 1023) / 1024;
    int t = threadIdx.x;
    int b = t * CH;
    int e = b + CH; if (e > N_NODES) e = N_NODES;
    int s = 0;
    for (int i = b; i < e; i++) {
        int d = g_deg[i];
        g_dinv[i] = rsqrtf((float)(d + 1));
        s += d;
    }
    part[t] = s;
    __syncthreads();
    for (int d = 1; d < 1024; d <<= 1) {
        int v = (t >= d) ? part[t - d] : 0;
        __syncthreads();
        part[t] += v;
        __syncthreads();
    }
    int run = (t > 0) ? part[t - 1] : 0;
    for (int i = b; i < e; i++) { g_off[i] = run; run += g_deg[i]; }
    if (t == 1023) g_off[N_NODES] = part[1023];
}

// fill CSR; low-index threads also transpose/split W (fused prepW)
__global__ void k_fill(const void* __restrict__ ei, const float* __restrict__ W0,
                       const float* __restrict__ W1, const float* __restrict__ W2) {
    int e = blockIdx.x * blockDim.x + threadIdx.x;
    if (e < 3 * DIM * DIM) {
        int L = e >> 14;
        int idx = e & (DIM * DIM - 1);
        const float* W = (L == 0) ? W0 : (L == 1) ? W1 : W2;
        int k = idx >> 7, n = idx & 127;
        float v = W[idx];
        __nv_bfloat16 hi = __float2bfloat16_rn(v);
        float lo = v - __bfloat162float(hi);
        g_Whi[L * DIM * DIM + n * DIM + k] = hi;
        g_Wlo[L * DIM * DIM + n * DIM + k] = __float2bfloat16_rn(lo);
    }
    if (e >= N_EDGES) return;
    int s = ldidx(ei, e);
    int d = ldidx(ei, N_EDGES + e);
    int p = g_off[d] + atomicAdd(&g_cur[d], 1);
    g_csrc[p] = s;
    g_cnrm[p] = g_dinv[s] * g_dinv[d];
}

// ---------------- mma.sync GEMM: g_hw[m][n] = sum_k A[m][k] * W[k][n] ----------------
// bf16 split x split (3 products), fp32 register accumulators, fp16 output.
// Block: 128 threads (4 warps), tile M=64, N=128, K=128. Layer 0 stages from fp32 x.
#define SAS 272                 // smem row stride in BYTES (136 bf16)
#define SM_AH 0
#define SM_AL (SM_AH + 64 * SAS)
#define SM_WH (SM_AL + 64 * SAS)
#define SM_WL (SM_WH + 128 * SAS)
#define SM_TOT (SM_WL + 128 * SAS)

__device__ __forceinline__ void ldsm4(uint32_t addr, uint32_t* r) {
    asm volatile("ldmatrix.sync.aligned.m8n8.x4.shared.b16 {%0,%1,%2,%3}, [%4];"
                 : "=r"(r[0]), "=r"(r[1]), "=r"(r[2]), "=r"(r[3]) : "r"(addr));
}
__device__ __forceinline__ void mma16816(float* d, const uint32_t* a, uint32_t b0, uint32_t b1) {
    asm volatile(
        "mma.sync.aligned.m16n8k16.row.col.f32.bf16.bf16.f32 "
        "{%0,%1,%2,%3}, {%4,%5,%6,%7}, {%8,%9}, {%0,%1,%2,%3};"
        : "+f"(d[0]), "+f"(d[1]), "+f"(d[2]), "+f"(d[3])
        : "r"(a[0]), "r"(a[1]), "r"(a[2]), "r"(a[3]), "r"(b0), "r"(b1));
}

__global__ void __launch_bounds__(128) k_gemm_mma(int layer, const float* __restrict__ xsrc) {
    extern __shared__ char smem[];
    uint32_t sb = smem_u32(smem);
    int tid = threadIdx.x, wid = tid >> 5, lane = tid & 31;
    int m0 = blockIdx.x * 64;
    int valid = N_NODES - m0; if (valid > 64) valid = 64;

    // stage A hi/lo (64 x 128 bf16 each; 16 uint4 per row)
    if (xsrc) {
        #pragma unroll
        for (int i = tid; i < 1024; i += 128) {
            int r = i >> 4, c = i & 15;
            uint4 vh = make_uint4(0, 0, 0, 0), vl = make_uint4(0, 0, 0, 0);
            if (r < valid) {
                const float4* xr = (const float4*)(xsrc + (long long)(m0 + r) * DIM) + c * 2;
                float4 f0 = xr[0], f1 = xr[1];
                split2(f0.x, f0.y, vh.x, vl.x);
                split2(f0.z, f0.w, vh.y, vl.y);
                split2(f1.x, f1.y, vh.z, vl.z);
                split2(f1.z, f1.w, vh.w, vl.w);
            }
            *(uint4*)(smem + SM_AH + r * SAS + c * 16) = vh;
            *(uint4*)(smem + SM_AL + r * SAS + c * 16) = vl;
        }
    } else {
        const uint4* gh = (const uint4*)(g_Ahi + (long long)m0 * DIM);
        const uint4* gl = (const uint4*)(g_Alo + (long long)m0 * DIM);
        #pragma unroll
        for (int i = tid; i < 1024; i += 128) {
            int r = i >> 4, c = i & 15;
            uint4 vh = make_uint4(0, 0, 0, 0), vl = make_uint4(0, 0, 0, 0);
            if (r < valid) { vh = gh[r * 16 + c]; vl = gl[r * 16 + c]; }
            *(uint4*)(smem + SM_AH + r * SAS + c * 16) = vh;
            *(uint4*)(smem + SM_AL + r * SAS + c * 16) = vl;
        }
    }
    {
        const uint4* wh = (const uint4*)(g_Whi + layer * DIM * DIM);
        const uint4* wl = (const uint4*)(g_Wlo + layer * DIM * DIM);
        #pragma unroll
        for (int i = tid; i < 2048; i += 128) {
            int r = i >> 4, c = i & 15;
            *(uint4*)(smem + SM_WH + r * SAS + c * 16) = wh[i];
            *(uint4*)(smem + SM_WL + r * SAS + c * 16) = wl[i];
        }
    }
    __syncthreads();

    float acc[16][4];
    #pragma unroll
    for (int j = 0; j < 16; j++)
        #pragma unroll
        for (int q = 0; q < 4; q++) acc[j][q] = 0.f;

    int wm = wid * 16;
    uint32_t a_off = (uint32_t)((wm + (lane & 15)) * SAS + ((lane >> 4) << 3) * 2);
    uint32_t b_off = (uint32_t)(((lane & 7) + ((lane >> 4) << 3)) * SAS + (((lane >> 3) & 1) << 3) * 2);

    for (int kk = 0; kk < 8; kk++) {
        uint32_t kb = kk * 32;
        uint32_t ah[4], al[4];
        ldsm4(sb + SM_AH + a_off + kb, ah);
        ldsm4(sb + SM_AL + a_off + kb, al);
        #pragma unroll
        for (int nt = 0; nt < 8; nt++) {
            uint32_t bh[4], bl[4];
            uint32_t nrow = nt * 16 * SAS;
            ldsm4(sb + SM_WH + nrow + b_off + kb, bh);
            ldsm4(sb + SM_WL + nrow + b_off + kb, bl);
            mma16816(acc[2 * nt],     ah, bh[0], bh[1]);
            mma16816(acc[2 * nt + 1], ah, bh[2], bh[3]);
            mma16816(acc[2 * nt],     ah, bl[0], bl[1]);
            mma16816(acc[2 * nt + 1], ah, bl[2], bl[3]);
            mma16816(acc[2 * nt],     al, bh[0], bh[1]);
            mma16816(acc[2 * nt + 1], al, bh[2], bh[3]);
        }
    }

    // epilogue: fp16 output
    int r0 = m0 + wm + (lane >> 2);
    int cb = (lane & 3) * 2;
    if (r0 < N_NODES) {
        __half* d = g_hw + (long long)r0 * DIM;
        #pragma unroll
        for (int j = 0; j < 16; j++)
            *(__half2*)(d + j * 8 + cb) = __floats2half2_rn(acc[j][0], acc[j][1]);
    }
    if (r0 + 8 < N_NODES) {
        __half* d = g_hw + (long long)(r0 + 8) * DIM;
        #pragma unroll
        for (int j = 0; j < 16; j++)
            *(__half2*)(d + j * 8 + cb) = __floats2half2_rn(acc[j][2], acc[j][3]);
    }
}

// ---------------- SpMM: fp16 gather (8 in flight, unpadded), fp32 acc, relu, split out ----
__device__ __forceinline__ void acc_edge(float4& acc, float n, uint2 v) {
    float2 a = h2f2(v.x), b = h2f2(v.y);
    acc.x += n * a.x; acc.y += n * a.y; acc.z += n * b.x; acc.w += n * b.y;
}

__global__ void __launch_bounds__(256) k_spmm(const float* __restrict__ bias) {
    int warp = (blockIdx.x * blockDim.x + threadIdx.x) >> 5;
    int lane = threadIdx.x & 31;
    if (warp >= N_NODES) return;
    int i = warp;

    float di = g_dinv[i];
    float sl = di * di;
    float4 acc;
    {
        uint2 v = ((const uint2*)(g_hw + (long long)i * DIM))[lane];
        float2 a = h2f2(v.x), b = h2f2(v.y);
        acc = make_float4(sl * a.x, sl * a.y, sl * b.x, sl * b.y);
    }

    int p = g_off[i], pe = g_off[i + 1];
    for (; p + 8 <= pe; p += 8) {
        int   s0 = g_csrc[p],     s1 = g_csrc[p + 1];
        int   s2 = g_csrc[p + 2], s3 = g_csrc[p + 3];
        int   s4 = g_csrc[p + 4], s5 = g_csrc[p + 5];
        int   s6 = g_csrc[p + 6], s7 = g_csrc[p + 7];
        float n0 = g_cnrm[p],     n1 = g_cnrm[p + 1];
        float n2 = g_cnrm[p + 2], n3 = g_cnrm[p + 3];
        float n4 = g_cnrm[p + 4], n5 = g_cnrm[p + 5];
        float n6 = g_cnrm[p + 6], n7 = g_cnrm[p + 7];
        uint2 v0 = ((const uint2*)(g_hw + (long long)s0 * DIM))[lane];
        uint2 v1 = ((const uint2*)(g_hw + (long long)s1 * DIM))[lane];
        uint2 v2 = ((const uint2*)(g_hw + (long long)s2 * DIM))[lane];
        uint2 v3 = ((const uint2*)(g_hw + (long long)s3 * DIM))[lane];
        uint2 v4 = ((const uint2*)(g_hw + (long long)s4 * DIM))[lane];
        uint2 v5 = ((const uint2*)(g_hw + (long long)s5 * DIM))[lane];
        uint2 v6 = ((const uint2*)(g_hw + (long long)s6 * DIM))[lane];
        uint2 v7 = ((const uint2*)(g_hw + (long long)s7 * DIM))[lane];
        acc_edge(acc, n0, v0);
        acc_edge(acc, n1, v1);
        acc_edge(acc, n2, v2);
        acc_edge(acc, n3, v3);
        acc_edge(acc, n4, v4);
        acc_edge(acc, n5, v5);
        acc_edge(acc, n6, v6);
        acc_edge(acc, n7, v7);
    }
    for (; p + 4 <= pe; p += 4) {
        int   s0 = g_csrc[p],     s1 = g_csrc[p + 1];
        int   s2 = g_csrc[p + 2], s3 = g_csrc[p + 3];
        float n0 = g_cnrm[p],     n1 = g_cnrm[p + 1];
        float n2 = g_cnrm[p + 2], n3 = g_cnrm[p + 3];
        uint2 v0 = ((const uint2*)(g_hw + (long long)s0 * DIM))[lane];
        uint2 v1 = ((const uint2*)(g_hw + (long long)s1 * DIM))[lane];
        uint2 v2 = ((const uint2*)(g_hw + (long long)s2 * DIM))[lane];
        uint2 v3 = ((const uint2*)(g_hw + (long long)s3 * DIM))[lane];
        acc_edge(acc, n0, v0);
        acc_edge(acc, n1, v1);
        acc_edge(acc, n2, v2);
        acc_edge(acc, n3, v3);
    }
    for (; p < pe; p++) {
        int s = g_csrc[p];
        float n = g_cnrm[p];
        uint2 v = ((const uint2*)(g_hw + (long long)s * DIM))[lane];
        acc_edge(acc, n, v);
    }

    float4 bv = ((const float4*)bias)[lane];
    acc.x = fmaxf(acc.x + bv.x, 0.f);
    acc.y = fmaxf(acc.y + bv.y, 0.f);
    acc.z = fmaxf(acc.z + bv.z, 0.f);
    acc.w = fmaxf(acc.w + bv.w, 0.f);

    // bf16 split store for next layer's GEMM (and pool)
    uint2 ph, pl;
    split2(acc.x, acc.y, ph.x, pl.x);
    split2(acc.z, acc.w, ph.y, pl.y);
    ((uint2*)g_Ahi)[(long long)i * 32 + lane] = ph;
    ((uint2*)g_Alo)[(long long)i * 32 + lane] = pl;
}

// ---------------- global mean pool (batch is sorted; no atomics) ----------------
__device__ __forceinline__ int lbound(const void* __restrict__ b, int key) {
    int lo = 0, hi = N_NODES;
    while (lo < hi) {
        int mid = (lo + hi) >> 1;
        if (ldidx(b, mid) < key) lo = mid + 1; else hi = mid;
    }
    return lo;
}
__global__ void k_pool(const void* __restrict__ batch) {
    int g = blockIdx.x / PCH;
    int c = blockIdx.x % PCH;
    int t = threadIdx.x;
    int start = lbound(batch, g);
    int end   = lbound(batch, g + 1);
    int len = end - start;
    int rs = start + (int)((long long)len * c / PCH);
    int re = start + (int)((long long)len * (c + 1) / PCH);
    float s = 0.f;
    for (int r = rs; r < re; r++) {
        long long idx = (long long)r * DIM + t;
        s += __bfloat162float(g_Ahi[idx]) + __bfloat162float(g_Alo[idx]);
    }
    g_pool[(c * NGRAPH + g) * DIM + t] = s;
}
__global__ void k_pool_div(const void* __restrict__ batch, float* __restrict__ out) {
    int g = blockIdx.x;
    int t = threadIdx.x;
    float s = 0.f;
    #pragma unroll
    for (int c = 0; c < PCH; c++) s += g_pool[(c * NGRAPH + g) * DIM + t];
    int start = lbound(batch, g);
    int end   = lbound(batch, g + 1);
    float cnt = (float)(end - start);
    if (cnt < 1.f) cnt = 1.f;
    out[g * DIM + t] = s / cnt;
}

// ---------------- launch ----------------
extern "C" void kernel_launch(void* const* d_in, const int* in_sizes, int n_in,
                              void* d_out, int out_size) {
    (void)out_size;
    const float* x = 0; const void* ei = 0; const void* batch = 0;
    const float* W[3] = {0, 0, 0}; const float* b[3] = {0, 0, 0};
    int nw = 0, nb = 0;
    for (int i = 0; i < n_in; i++) {
        int sz = in_sizes[i];
        if      (sz == N_NODES * DIM) x     = (const float*)d_in[i];
        else if (sz == 2 * N_EDGES)   ei    = d_in[i];
        else if (sz == N_NODES)       batch = d_in[i];
        else if (sz == DIM * DIM)     { if (nw < 3) W[nw++] = (const float*)d_in[i]; }
        else if (sz == DIM)           { if (nb < 3) b[nb++] = (const float*)d_in[i]; }
    }
    float* out = (float*)d_out;

    cudaFuncSetAttribute(k_gemm_mma, cudaFuncAttributeMaxDynamicSharedMemorySize, SM_TOT);

    const int NT = 256;
    int nblk = (N_NODES + NT - 1) / NT;
    int eblk = (N_EDGES + NT - 1) / NT;
    int spmm_blocks = (N_NODES * 32 + NT - 1) / NT;
    int gemm_blocks = (N_NODES + 63) / 64;  // 782

    // preprocess (4 launches)
    k_init<<<nblk, NT>>>((const int*)ei);
    k_degree<<<eblk, NT>>>(ei);
    k_scan<<<1, 1024>>>();
    k_fill<<<eblk, NT>>>(ei, W[0], W[1], W[2]);

    // layers (6 launches); layer 0 stages directly from fp32 x
    k_gemm_mma<<<gemm_blocks, 128, SM_TOT>>>(0, x);
    k_spmm<<<spmm_blocks, NT>>>(b[0]);
    k_gemm_mma<<<gemm_blocks, 128, SM_TOT>>>(1, nullptr);
    k_spmm<<<spmm_blocks, NT>>>(b[1]);
    k_gemm_mma<<<gemm_blocks, 128, SM_TOT>>>(2, nullptr);
    k_spmm<<<spmm_blocks, NT>>>(b[2]);

    // pool (2 launches, no atomics)
    k_pool<<<NGRAPH * PCH, DIM>>>(batch);
    k_pool_div<<<NGRAPH, DIM>>>(batch, out);
}